// round 14
// baseline (speedup 1.0000x reference)
#include <cuda_runtime.h>
#include <cuda_fp16.h>
#include <cstdint>

// Problem shape (fixed per metadata):
//   X0 [4,1024,256] f32, t [4,1] f32, Wc_w [128,256] f32, Wc_b [128] f32,
//   w [128] f32, A [64,128,6] f32, Bp [64,128,6] f32  ->  out [4,1024,64] f32
#define B_   4
#define S_   1024
#define ROWS 4096        // B_*S_
#define DIN  256
#define Q_   128
#define KF   6
#define DOUT 64
#define KSL  1536        // GEMM2: 1 fp16 slot per feature

// Scratch (no device allocs allowed)
__device__ float  g_angle[ROWS * Q_];          // 2 MB
__device__ __half g_bh[DOUT * KSL];            // 192 KB  [d][k] fp16 coeffs

// ---------------------------------------------------------------------------
// m16n8k16 fp16 MMA + ldmatrix helpers
// ---------------------------------------------------------------------------
__device__ __forceinline__ void mma16816(float* c, const uint32_t* a,
                                         const uint32_t* b) {
    asm volatile(
        "mma.sync.aligned.m16n8k16.row.col.f32.f16.f16.f32 "
        "{%0,%1,%2,%3}, {%4,%5,%6,%7}, {%8,%9}, {%0,%1,%2,%3};"
        : "+f"(c[0]), "+f"(c[1]), "+f"(c[2]), "+f"(c[3])
        : "r"(a[0]), "r"(a[1]), "r"(a[2]), "r"(a[3]), "r"(b[0]), "r"(b[1]));
}
__device__ __forceinline__ void ldsm_x4(uint32_t* r, uint32_t addr) {
    asm volatile("ldmatrix.sync.aligned.m8n8.x4.shared.b16 {%0,%1,%2,%3}, [%4];"
                 : "=r"(r[0]), "=r"(r[1]), "=r"(r[2]), "=r"(r[3]) : "r"(addr));
}
__device__ __forceinline__ uint32_t smem_u32(const void* p) {
    uint32_t a;
    asm("{ .reg .u64 t; cvta.to.shared.u64 t, %1; cvt.u32.u64 %0, t; }"
        : "=r"(a) : "l"(p));
    return a;
}

// ---------------------------------------------------------------------------
// Kernel 1: angle GEMM (R13 variant, unchanged — measured ~8.2us).
// ---------------------------------------------------------------------------
#define KP1 72

__global__ __launch_bounds__(128) void angle_kernel(
    const float* __restrict__ X0, const float* __restrict__ W,
    const float* __restrict__ bias, const float* __restrict__ wvec,
    const float* __restrict__ tvec,
    const float* __restrict__ A, const float* __restrict__ Bp)
{
    __shared__ __align__(16) __half Ws1[2][Q_][KP1];   // 36 KB
    __shared__ __align__(16) __half Ax1[2][32][KP1];   //  9.2 KB

    int tid  = threadIdx.x;
    int lane = tid & 31;
    int w    = tid >> 5;              // warp 0..3, q range w*32 .. +31
    int r0   = blockIdx.x * 32;
    int ra   = lane >> 2;
    int cc   = 2 * (lane & 3);
    int lrow = (lane & 7) + ((lane >> 3) & 1) * 8;   // ldmatrix row-in-tile
    int lco  = (lane >> 4) * 8;                      // ldmatrix col offset

    float acc[2][4][4] = {};          // [mtile][ntile][frag]
    int xrow = tid >> 2;              // A staging row 0..31
    int kgrp = (tid & 3) * 8;         // f32 k offset (8 floats/thread)

    auto stageA = [&](const float4& x0, const float4& x1, int buf) {
        float xf[8] = {x0.x, x0.y, x0.z, x0.w, x1.x, x1.y, x1.z, x1.w};
        uint32_t ph[4], pl[4];
        #pragma unroll
        for (int j = 0; j < 4; j++) {
            float a0 = xf[2 * j], a1 = xf[2 * j + 1];
            __half h0 = __float2half_rn(a0);
            __half l0 = __float2half_rn(a0 - __half2float(h0));
            __half h1 = __float2half_rn(a1);
            __half l1 = __float2half_rn(a1 - __half2float(h1));
            __half2 hh = __halves2half2(h0, h1);
            __half2 ll = __halves2half2(l0, l1);
            ph[j] = *(uint32_t*)&hh;
            pl[j] = *(uint32_t*)&ll;
        }
        *(uint4*)&Ax1[buf][xrow][kgrp]      = make_uint4(ph[0], ph[1], ph[2], ph[3]);
        *(uint4*)&Ax1[buf][xrow][32 + kgrp] = make_uint4(pl[0], pl[1], pl[2], pl[3]);
    };
    auto stageW = [&](const float4* nwf, int buf) {
        const float* wf = (const float*)nwf;
        uint32_t whp[16], wlp[16];
        #pragma unroll
        for (int j = 0; j < 16; j++) {
            float a0 = wf[2 * j], a1 = wf[2 * j + 1];
            __half h0 = __float2half_rn(a0);
            __half l0 = __float2half_rn(a0 - __half2float(h0));
            __half h1 = __float2half_rn(a1);
            __half l1 = __float2half_rn(a1 - __half2float(h1));
            __half2 hh = __halves2half2(h0, h1);
            __half2 ll = __halves2half2(l0, l1);
            whp[j] = *(uint32_t*)&hh;
            wlp[j] = *(uint32_t*)&ll;
        }
        #pragma unroll
        for (int g = 0; g < 4; g++) {
            *(uint4*)&Ws1[buf][tid][g * 8] =
                make_uint4(whp[4*g], whp[4*g+1], whp[4*g+2], whp[4*g+3]);
            *(uint4*)&Ws1[buf][tid][32 + g * 8] =
                make_uint4(wlp[4*g], wlp[4*g+1], wlp[4*g+2], wlp[4*g+3]);
        }
    };

    // ---- prologue: stage chunk 0, prefetch chunk 1 ----
    float4 nx0 = *(const float4*)&X0[(r0 + xrow) * DIN + kgrp];
    float4 nx1 = *(const float4*)&X0[(r0 + xrow) * DIN + kgrp + 4];
    float4 nwf[8];
    #pragma unroll
    for (int j = 0; j < 8; j++)
        nwf[j] = *(const float4*)&W[tid * DIN + j * 4];
    stageA(nx0, nx1, 0);
    stageW(nwf, 0);
    nx0 = *(const float4*)&X0[(r0 + xrow) * DIN + 32 + kgrp];
    nx1 = *(const float4*)&X0[(r0 + xrow) * DIN + 32 + kgrp + 4];
    #pragma unroll
    for (int j = 0; j < 8; j++)
        nwf[j] = *(const float4*)&W[tid * DIN + 32 + j * 4];
    __syncthreads();

    for (int c = 0; c < 8; c++) {
        if (c < 7) {
            stageA(nx0, nx1, (c + 1) & 1);
            stageW(nwf, (c + 1) & 1);
            if (c < 6) {
                nx0 = *(const float4*)&X0[(r0 + xrow) * DIN + (c + 2) * 32 + kgrp];
                nx1 = *(const float4*)&X0[(r0 + xrow) * DIN + (c + 2) * 32 + kgrp + 4];
                #pragma unroll
                for (int j = 0; j < 8; j++)
                    nwf[j] = *(const float4*)&W[tid * DIN + (c + 2) * 32 + j * 4];
            }
        }

        uint32_t axb = smem_u32(&Ax1[c & 1][0][0]);
        const __half (*Ws)[KP1] = Ws1[c & 1];
        #pragma unroll
        for (int kt = 0; kt < 2; kt++) {
            int khb = kt * 16;            // xh col base
            int klb = 32 + kt * 16;       // xl col base
            uint32_t A0h[4], A1h[4], A0l[4], A1l[4];
            ldsm_x4(A0h, axb + (uint32_t)((lrow * KP1 + khb + lco) * 2));
            ldsm_x4(A1h, axb + (uint32_t)(((16 + lrow) * KP1 + khb + lco) * 2));
            ldsm_x4(A0l, axb + (uint32_t)((lrow * KP1 + klb + lco) * 2));
            ldsm_x4(A1l, axb + (uint32_t)(((16 + lrow) * KP1 + klb + lco) * 2));
            int kh = khb + cc, kl = klb + cc;
            #pragma unroll
            for (int n = 0; n < 4; n++) {
                int q0 = w * 32 + n * 8 + ra;
                uint32_t Bh[2], Bl[2];
                Bh[0] = *(const uint32_t*)&Ws[q0][kh];
                Bh[1] = *(const uint32_t*)&Ws[q0][kh + 8];
                Bl[0] = *(const uint32_t*)&Ws[q0][kl];
                Bl[1] = *(const uint32_t*)&Ws[q0][kl + 8];
                mma16816(acc[0][n], A0h, Bh);   // xh*wh
                mma16816(acc[1][n], A1h, Bh);
                mma16816(acc[0][n], A0h, Bl);   // xh*wl
                mma16816(acc[1][n], A1h, Bl);
                mma16816(acc[0][n], A0l, Bh);   // xl*wh
                mma16816(acc[1][n], A1l, Bh);
            }
        }
        __syncthreads();
    }

    // ---- epilogue: + bias + w*t -> g_angle ----
    float tb = tvec[r0 >> 10];
    #pragma unroll
    for (int n = 0; n < 4; n++) {
        int q = w * 32 + n * 8 + cc;
        float b0 = __ldg(&bias[q])     + __ldg(&wvec[q]) * tb;
        float b1 = __ldg(&bias[q + 1]) + __ldg(&wvec[q + 1]) * tb;
        #pragma unroll
        for (int m = 0; m < 2; m++) {
            int rr = r0 + m * 16 + ra;
            float* a4 = acc[m][n];
            *(float2*)&g_angle[rr * Q_ + q]       = make_float2(a4[0] + b0, a4[1] + b1);
            *(float2*)&g_angle[(rr + 8) * Q_ + q] = make_float2(a4[2] + b0, a4[3] + b1);
        }
    }

    // ---- tail: this CTA's 384-element slice of the A,Bp fold (g_bh) ----
    #pragma unroll
    for (int j = 0; j < 3; j++) {
        int i = blockIdx.x * 384 + j * 128 + tid;     // 0 .. 49151
        int d   = i / (Q_ * KF);
        int rem = i - d * (Q_ * KF);                  // q*6 + h
        float a = A[i], b = Bp[i];
        float sb, cb;
        __sincosf(b, &sb, &cb);
        __half2 hv = __floats2half2_rn(a * cb, a * sb);
        *(uint32_t*)&g_bh[d * KSL + rem * 2] = *(uint32_t*)&hv;
    }
}

// ---------------------------------------------------------------------------
// Kernel 2: fused feature-gen + HMMA GEMM2 — single barrier per chunk at
// FULL 192-slot chunk size. B lives in a full-size smem buffer filled
// incrementally (region c+1 staged while MMA reads region c; regions
// disjoint -> no WAR hazard, no double buffer). A/feature tile double-
// buffered. A frags via ldmatrix.x4.
// Dynamic smem: As 2x[32][200] (25600 B) + Bs [64][1544] (197632 B)
//             = 223232 B (<= 227 KB sm_100 cap).
// ---------------------------------------------------------------------------
#define KPAD    200
#define BST     1544      // Bs stride in halves; 1544 % 64 == 8 -> same
                          // bank-offset-4 pattern as KPAD=200 (proven)
#define CHUNK_K 192
#define NCHUNK  8
#define FUSE_SMEM (2 * 32 * KPAD * 2 + DOUT * BST * 2)   // 223232

__global__ __launch_bounds__(128) void fuse_kernel(float* __restrict__ out)
{
    extern __shared__ __align__(16) char sm[];
    __half* AsBase = (__half*)sm;                         // 2 x [32][KPAD]
    __half* BsBase = (__half*)(sm + 2 * 32 * KPAD * 2);   // [64][BST]

    int tid  = threadIdx.x;
    int lane = tid & 31;
    int w    = tid >> 5;
    int r0   = blockIdx.x * 32;
    int row  = lane;                  // featgen row
    int qlb  = w * 4;                 // featgen local-q base (4 q per thread)
    int ra   = lane >> 2;
    int cc   = 2 * (lane & 3);
    int lrow = (lane & 7) + ((lane >> 3) & 1) * 8;
    int lco  = (lane >> 4) * 8;

    float acc[2][2][4] = {};

    auto featgen = [&](const float4& ang, int buf) {
        float af[4] = {ang.x, ang.y, ang.z, ang.w};
        __half* As = AsBase + buf * 32 * KPAD;
        #pragma unroll
        for (int p = 0; p < 4; p++) {
            float a = af[p];
            // Cody-Waite reduction mod 2*pi (C1=6.28125: 9 mantissa bits)
            float n = rintf(a * 0.15915494309189535f);
            float rr = fmaf(n, -6.28125f, a);
            rr = fmaf(n, -1.9353071795864769e-3f, rr);
            float s1, c1;
            __sincosf(rr, &s1, &c1);
            float f[12];
            f[0] = s1; f[1] = c1;
            float sk = s1, ck = c1;
            #pragma unroll
            for (int h = 1; h < KF; h++) {
                float sn = fmaf(sk, c1, ck * s1);
                float cn = fmaf(ck, c1, -sk * s1);
                f[2 * h] = sn; f[2 * h + 1] = cn;
                sk = sn; ck = cn;
            }
            uint32_t hv[6];
            #pragma unroll
            for (int g = 0; g < 6; g++) {
                __half2 h2 = __floats2half2_rn(f[2 * g], f[2 * g + 1]);
                hv[g] = *(uint32_t*)&h2;
            }
            uint64_t* dst = (uint64_t*)&As[row * KPAD + (qlb + p) * 12];
            dst[0] = (uint64_t)hv[0] | ((uint64_t)hv[1] << 32);
            dst[1] = (uint64_t)hv[2] | ((uint64_t)hv[3] << 32);
            dst[2] = (uint64_t)hv[4] | ((uint64_t)hv[5] << 32);
        }
    };
    auto loadB = [&](uint4* nB, int c) {
        #pragma unroll
        for (int r = 0; r < 12; r++) {
            int idx = tid + 128 * r;
            int d   = idx / 24;
            int kc  = idx - d * 24;
            nB[r] = *(const uint4*)&g_bh[d * KSL + c * CHUNK_K + kc * 8];
        }
    };
    auto stageB = [&](const uint4* nB, int c) {
        #pragma unroll
        for (int r = 0; r < 12; r++) {
            int idx = tid + 128 * r;
            int d   = idx / 24;
            int kc  = idx - d * 24;
            *(uint4*)&BsBase[d * BST + c * CHUNK_K + kc * 8] = nB[r];
        }
    };

    // ---- prologue: stage chunk 0, prefetch chunk 1 ----
    uint4 nB[12];
    loadB(nB, 0);
    float4 nAng = *(const float4*)&g_angle[(r0 + row) * Q_ + qlb];
    featgen(nAng, 0);
    stageB(nB, 0);
    loadB(nB, 1);
    nAng = *(const float4*)&g_angle[(r0 + row) * Q_ + 16 + qlb];
    __syncthreads();

    for (int c = 0; c < NCHUNK; c++) {
        // ---- stage chunk c+1 (overlaps MMA below; disjoint B region) ----
        if (c < NCHUNK - 1) {
            featgen(nAng, (c + 1) & 1);
            stageB(nB, c + 1);
            if (c < NCHUNK - 2) {
                loadB(nB, c + 2);
                nAng = *(const float4*)&g_angle[(r0 + row) * Q_ + (c + 2) * 16 + qlb];
            }
        }

        // ---- MMA(c): 12 ktiles x (2m x 2n) ----
        uint32_t asb = smem_u32(AsBase + (c & 1) * 32 * KPAD);
        const __half* Bsv = BsBase;
        #pragma unroll
        for (int kt = 0; kt < 12; kt++) {
            int k0 = c * CHUNK_K + kt * 16 + cc;
            uint32_t A0[4], A1[4];
            ldsm_x4(A0, asb + (uint32_t)((lrow * KPAD + kt * 16 + lco) * 2));
            ldsm_x4(A1, asb + (uint32_t)(((16 + lrow) * KPAD + kt * 16 + lco) * 2));
            int d0 = w * 16 + ra;
            uint32_t Bf0[2], Bf1[2];
            Bf0[0] = *(const uint32_t*)&Bsv[d0 * BST + k0];
            Bf0[1] = *(const uint32_t*)&Bsv[d0 * BST + k0 + 8];
            Bf1[0] = *(const uint32_t*)&Bsv[(d0 + 8) * BST + k0];
            Bf1[1] = *(const uint32_t*)&Bsv[(d0 + 8) * BST + k0 + 8];
            mma16816(acc[0][0], A0, Bf0);
            mma16816(acc[0][1], A0, Bf1);
            mma16816(acc[1][0], A1, Bf0);
            mma16816(acc[1][1], A1, Bf1);
        }
        __syncthreads();
    }

    // ---- epilogue ----
    int orow = r0 + ra;
    int ocol = w * 16 + cc;
    #pragma unroll
    for (int m = 0; m < 2; m++) {
        #pragma unroll
        for (int nt = 0; nt < 2; nt++) {
            float* a4 = acc[m][nt];
            int rr  = orow + m * 16;
            int ccg = ocol + nt * 8;
            *(float2*)&out[rr * DOUT + ccg]       = make_float2(a4[0], a4[1]);
            *(float2*)&out[(rr + 8) * DOUT + ccg] = make_float2(a4[2], a4[3]);
        }
    }
}

// ---------------------------------------------------------------------------
extern "C" void kernel_launch(void* const* d_in, const int* in_sizes, int n_in,
                              void* d_out, int out_size) {
    const float* X0   = (const float*)d_in[0];
    const float* tvec = (const float*)d_in[1];
    const float* Wc_w = (const float*)d_in[2];
    const float* Wc_b = (const float*)d_in[3];
    const float* wvec = (const float*)d_in[4];
    const float* A    = (const float*)d_in[5];
    const float* Bp   = (const float*)d_in[6];
    float* out = (float*)d_out;

    static int attr_set = 0;
    if (!attr_set) {
        cudaFuncSetAttribute(fuse_kernel,
                             cudaFuncAttributeMaxDynamicSharedMemorySize,
                             FUSE_SMEM);
        attr_set = 1;
    }

    angle_kernel<<<ROWS / 32, 128>>>(X0, Wc_w, Wc_b, wvec, tvec, A, Bp);
    fuse_kernel<<<ROWS / 32, 128, FUSE_SMEM>>>(out);
}

// round 15
// speedup vs baseline: 1.0908x; 1.0908x over previous
#include <cuda_runtime.h>
#include <cuda_fp16.h>
#include <cstdint>

// Problem shape (fixed per metadata):
//   X0 [4,1024,256] f32, t [4,1] f32, Wc_w [128,256] f32, Wc_b [128] f32,
//   w [128] f32, A [64,128,6] f32, Bp [64,128,6] f32  ->  out [4,1024,64] f32
#define B_   4
#define S_   1024
#define ROWS 4096        // B_*S_
#define DIN  256
#define Q_   128
#define KF   6
#define DOUT 64
#define KSL  1536        // GEMM2: 1 fp16 slot per feature

// Scratch (no device allocs allowed)
__device__ float  g_angle[ROWS * Q_];          // 2 MB
__device__ __half g_bh[DOUT * KSL];            // 192 KB  [d][k] fp16 coeffs

// ---------------------------------------------------------------------------
// m16n8k16 fp16 MMA + ldmatrix helpers
// ---------------------------------------------------------------------------
__device__ __forceinline__ void mma16816(float* c, const uint32_t* a,
                                         const uint32_t* b) {
    asm volatile(
        "mma.sync.aligned.m16n8k16.row.col.f32.f16.f16.f32 "
        "{%0,%1,%2,%3}, {%4,%5,%6,%7}, {%8,%9}, {%0,%1,%2,%3};"
        : "+f"(c[0]), "+f"(c[1]), "+f"(c[2]), "+f"(c[3])
        : "r"(a[0]), "r"(a[1]), "r"(a[2]), "r"(a[3]), "r"(b[0]), "r"(b[1]));
}
__device__ __forceinline__ void ldsm_x4(uint32_t* r, uint32_t addr) {
    asm volatile("ldmatrix.sync.aligned.m8n8.x4.shared.b16 {%0,%1,%2,%3}, [%4];"
                 : "=r"(r[0]), "=r"(r[1]), "=r"(r[2]), "=r"(r[3]) : "r"(addr));
}
__device__ __forceinline__ uint32_t smem_u32(const void* p) {
    uint32_t a;
    asm("{ .reg .u64 t; cvta.to.shared.u64 t, %1; cvt.u32.u64 %0, t; }"
        : "=r"(a) : "l"(p));
    return a;
}

// ---------------------------------------------------------------------------
// Kernel 1: angle GEMM (R13 variant — measured ~8.2us) + zero-init of out
// in the tail (so fuse can atomicAdd partial sums).
// ---------------------------------------------------------------------------
#define KP1 72

__global__ __launch_bounds__(128) void angle_kernel(
    const float* __restrict__ X0, const float* __restrict__ W,
    const float* __restrict__ bias, const float* __restrict__ wvec,
    const float* __restrict__ tvec,
    const float* __restrict__ A, const float* __restrict__ Bp,
    float* __restrict__ out)
{
    __shared__ __align__(16) __half Ws1[2][Q_][KP1];   // 36 KB
    __shared__ __align__(16) __half Ax1[2][32][KP1];   //  9.2 KB

    int tid  = threadIdx.x;
    int lane = tid & 31;
    int w    = tid >> 5;              // warp 0..3, q range w*32 .. +31
    int r0   = blockIdx.x * 32;
    int ra   = lane >> 2;
    int cc   = 2 * (lane & 3);
    int lrow = (lane & 7) + ((lane >> 3) & 1) * 8;   // ldmatrix row-in-tile
    int lco  = (lane >> 4) * 8;                      // ldmatrix col offset

    float acc[2][4][4] = {};          // [mtile][ntile][frag]
    int xrow = tid >> 2;              // A staging row 0..31
    int kgrp = (tid & 3) * 8;         // f32 k offset (8 floats/thread)

    auto stageA = [&](const float4& x0, const float4& x1, int buf) {
        float xf[8] = {x0.x, x0.y, x0.z, x0.w, x1.x, x1.y, x1.z, x1.w};
        uint32_t ph[4], pl[4];
        #pragma unroll
        for (int j = 0; j < 4; j++) {
            float a0 = xf[2 * j], a1 = xf[2 * j + 1];
            __half h0 = __float2half_rn(a0);
            __half l0 = __float2half_rn(a0 - __half2float(h0));
            __half h1 = __float2half_rn(a1);
            __half l1 = __float2half_rn(a1 - __half2float(h1));
            __half2 hh = __halves2half2(h0, h1);
            __half2 ll = __halves2half2(l0, l1);
            ph[j] = *(uint32_t*)&hh;
            pl[j] = *(uint32_t*)&ll;
        }
        *(uint4*)&Ax1[buf][xrow][kgrp]      = make_uint4(ph[0], ph[1], ph[2], ph[3]);
        *(uint4*)&Ax1[buf][xrow][32 + kgrp] = make_uint4(pl[0], pl[1], pl[2], pl[3]);
    };
    auto stageW = [&](const float4* nwf, int buf) {
        const float* wf = (const float*)nwf;
        uint32_t whp[16], wlp[16];
        #pragma unroll
        for (int j = 0; j < 16; j++) {
            float a0 = wf[2 * j], a1 = wf[2 * j + 1];
            __half h0 = __float2half_rn(a0);
            __half l0 = __float2half_rn(a0 - __half2float(h0));
            __half h1 = __float2half_rn(a1);
            __half l1 = __float2half_rn(a1 - __half2float(h1));
            __half2 hh = __halves2half2(h0, h1);
            __half2 ll = __halves2half2(l0, l1);
            whp[j] = *(uint32_t*)&hh;
            wlp[j] = *(uint32_t*)&ll;
        }
        #pragma unroll
        for (int g = 0; g < 4; g++) {
            *(uint4*)&Ws1[buf][tid][g * 8] =
                make_uint4(whp[4*g], whp[4*g+1], whp[4*g+2], whp[4*g+3]);
            *(uint4*)&Ws1[buf][tid][32 + g * 8] =
                make_uint4(wlp[4*g], wlp[4*g+1], wlp[4*g+2], wlp[4*g+3]);
        }
    };

    // ---- prologue: stage chunk 0, prefetch chunk 1 ----
    float4 nx0 = *(const float4*)&X0[(r0 + xrow) * DIN + kgrp];
    float4 nx1 = *(const float4*)&X0[(r0 + xrow) * DIN + kgrp + 4];
    float4 nwf[8];
    #pragma unroll
    for (int j = 0; j < 8; j++)
        nwf[j] = *(const float4*)&W[tid * DIN + j * 4];
    stageA(nx0, nx1, 0);
    stageW(nwf, 0);
    nx0 = *(const float4*)&X0[(r0 + xrow) * DIN + 32 + kgrp];
    nx1 = *(const float4*)&X0[(r0 + xrow) * DIN + 32 + kgrp + 4];
    #pragma unroll
    for (int j = 0; j < 8; j++)
        nwf[j] = *(const float4*)&W[tid * DIN + 32 + j * 4];
    __syncthreads();

    for (int c = 0; c < 8; c++) {
        if (c < 7) {
            stageA(nx0, nx1, (c + 1) & 1);
            stageW(nwf, (c + 1) & 1);
            if (c < 6) {
                nx0 = *(const float4*)&X0[(r0 + xrow) * DIN + (c + 2) * 32 + kgrp];
                nx1 = *(const float4*)&X0[(r0 + xrow) * DIN + (c + 2) * 32 + kgrp + 4];
                #pragma unroll
                for (int j = 0; j < 8; j++)
                    nwf[j] = *(const float4*)&W[tid * DIN + (c + 2) * 32 + j * 4];
            }
        }

        uint32_t axb = smem_u32(&Ax1[c & 1][0][0]);
        const __half (*Ws)[KP1] = Ws1[c & 1];
        #pragma unroll
        for (int kt = 0; kt < 2; kt++) {
            int khb = kt * 16;            // xh col base
            int klb = 32 + kt * 16;       // xl col base
            uint32_t A0h[4], A1h[4], A0l[4], A1l[4];
            ldsm_x4(A0h, axb + (uint32_t)((lrow * KP1 + khb + lco) * 2));
            ldsm_x4(A1h, axb + (uint32_t)(((16 + lrow) * KP1 + khb + lco) * 2));
            ldsm_x4(A0l, axb + (uint32_t)((lrow * KP1 + klb + lco) * 2));
            ldsm_x4(A1l, axb + (uint32_t)(((16 + lrow) * KP1 + klb + lco) * 2));
            int kh = khb + cc, kl = klb + cc;
            #pragma unroll
            for (int n = 0; n < 4; n++) {
                int q0 = w * 32 + n * 8 + ra;
                uint32_t Bh[2], Bl[2];
                Bh[0] = *(const uint32_t*)&Ws[q0][kh];
                Bh[1] = *(const uint32_t*)&Ws[q0][kh + 8];
                Bl[0] = *(const uint32_t*)&Ws[q0][kl];
                Bl[1] = *(const uint32_t*)&Ws[q0][kl + 8];
                mma16816(acc[0][n], A0h, Bh);   // xh*wh
                mma16816(acc[1][n], A1h, Bh);
                mma16816(acc[0][n], A0h, Bl);   // xh*wl
                mma16816(acc[1][n], A1h, Bl);
                mma16816(acc[0][n], A0l, Bh);   // xl*wh
                mma16816(acc[1][n], A1l, Bh);
            }
        }
        __syncthreads();
    }

    // ---- epilogue: + bias + w*t -> g_angle ----
    float tb = tvec[r0 >> 10];
    #pragma unroll
    for (int n = 0; n < 4; n++) {
        int q = w * 32 + n * 8 + cc;
        float b0 = __ldg(&bias[q])     + __ldg(&wvec[q]) * tb;
        float b1 = __ldg(&bias[q + 1]) + __ldg(&wvec[q + 1]) * tb;
        #pragma unroll
        for (int m = 0; m < 2; m++) {
            int rr = r0 + m * 16 + ra;
            float* a4 = acc[m][n];
            *(float2*)&g_angle[rr * Q_ + q]       = make_float2(a4[0] + b0, a4[1] + b1);
            *(float2*)&g_angle[(rr + 8) * Q_ + q] = make_float2(a4[2] + b0, a4[3] + b1);
        }
    }

    // ---- tail A: 384-element slice of the A,Bp fold (g_bh) ----
    #pragma unroll
    for (int j = 0; j < 3; j++) {
        int i = blockIdx.x * 384 + j * 128 + tid;     // 0 .. 49151
        int d   = i / (Q_ * KF);
        int rem = i - d * (Q_ * KF);                  // q*6 + h
        float a = A[i], b = Bp[i];
        float sb, cb;
        __sincosf(b, &sb, &cb);
        __half2 hv = __floats2half2_rn(a * cb, a * sb);
        *(uint32_t*)&g_bh[d * KSL + rem * 2] = *(uint32_t*)&hv;
    }

    // ---- tail B: zero this CTA's 2048-float slice of out (for atomics) ----
    {
        float4 z = make_float4(0.f, 0.f, 0.f, 0.f);
        float4* ob = (float4*)(out + blockIdx.x * 2048);
        #pragma unroll
        for (int j = 0; j < 4; j++)
            ob[tid + 128 * j] = z;
    }
}

// ---------------------------------------------------------------------------
// Kernel 2: fused feature-gen + HMMA GEMM2, K-SPLIT x2.
// 256 CTAs x 128 threads: CTA (r,h) = rows (bid>>1)*32..+31, q-half h=bid&1
// (q 64h..64h+63, k-slots 768h..768h+767), 4 chunks of 192 slots — per-chunk
// structure identical to the measured-best R10 loop. Partial V merged with
// red.global.add (out zeroed by angle tail). 2 CTAs/SM co-resident.
// ---------------------------------------------------------------------------
#define KPAD   200
#define CHUNK_K 192
#define NCHUNK  4

__global__ __launch_bounds__(128) void fuse_kernel(float* __restrict__ out)
{
    __shared__ __half As[32][KPAD];   // 12.8 KB
    __shared__ __half Bs[64][KPAD];   // 25.6 KB

    int tid  = threadIdx.x;
    int lane = tid & 31;
    int w    = tid >> 5;
    int r0   = (blockIdx.x >> 1) * 32;
    int kh   = blockIdx.x & 1;        // K half
    int qb   = kh * 64;               // global q base of this half
    int kb   = kh * 768;              // global k-slot base
    int row  = lane;                  // featgen row
    int qlb  = w * 4;                 // featgen local-q base (4 q per thread)

    float acc[2][2][4] = {};

    // prologue prefetch: chunk 0
    uint4 nB[12];
    #pragma unroll
    for (int r = 0; r < 12; r++) {
        int idx = tid + 128 * r;
        int d   = idx / 24;
        int kc  = idx - d * 24;
        nB[r] = *(const uint4*)&g_bh[d * KSL + kb + kc * 8];
    }
    float4 nAng = *(const float4*)&g_angle[(r0 + row) * Q_ + qb + qlb];

    for (int c = 0; c < NCHUNK; c++) {
        // ---- features for 4 q's -> fp16, STS ----
        {
            float af[4] = {nAng.x, nAng.y, nAng.z, nAng.w};
            #pragma unroll
            for (int p = 0; p < 4; p++) {
                float a = af[p];
                // Cody-Waite reduction mod 2*pi (C1=6.28125: 9 mantissa bits)
                float n = rintf(a * 0.15915494309189535f);
                float rr = fmaf(n, -6.28125f, a);
                rr = fmaf(n, -1.9353071795864769e-3f, rr);
                float s1, c1;
                __sincosf(rr, &s1, &c1);
                float f[12];
                f[0] = s1; f[1] = c1;
                float sk = s1, ck = c1;
                #pragma unroll
                for (int h = 1; h < KF; h++) {
                    float sn = fmaf(sk, c1, ck * s1);
                    float cn = fmaf(ck, c1, -sk * s1);
                    f[2 * h] = sn; f[2 * h + 1] = cn;
                    sk = sn; ck = cn;
                }
                uint32_t hv[6];
                #pragma unroll
                for (int g = 0; g < 6; g++) {
                    __half2 h2 = __floats2half2_rn(f[2 * g], f[2 * g + 1]);
                    hv[g] = *(uint32_t*)&h2;
                }
                int kl = (qlb + p) * 12;
                uint64_t* dst = (uint64_t*)&As[row][kl];
                dst[0] = (uint64_t)hv[0] | ((uint64_t)hv[1] << 32);
                dst[1] = (uint64_t)hv[2] | ((uint64_t)hv[3] << 32);
                dst[2] = (uint64_t)hv[4] | ((uint64_t)hv[5] << 32);
            }
        }
        // ---- stage B chunk ----
        #pragma unroll
        for (int r = 0; r < 12; r++) {
            int idx = tid + 128 * r;
            int d   = idx / 24;
            int kc  = idx - d * 24;
            *(uint4*)&Bs[d][kc * 8] = nB[r];
        }
        __syncthreads();

        // ---- prefetch next chunk ----
        if (c < NCHUNK - 1) {
            #pragma unroll
            for (int r = 0; r < 12; r++) {
                int idx = tid + 128 * r;
                int d   = idx / 24;
                int kc  = idx - d * 24;
                nB[r] = *(const uint4*)&g_bh[d * KSL + kb + (c + 1) * CHUNK_K + kc * 8];
            }
            nAng = *(const float4*)&g_angle[(r0 + row) * Q_ + qb + (c + 1) * 16 + qlb];
        }

        // ---- MMA: 12 ktiles x (2m x 2n) ----
        int ra = lane >> 2;
        int cc = 2 * (lane & 3);
        #pragma unroll
        for (int kt = 0; kt < 12; kt++) {
            int k0 = kt * 16 + cc;
            uint32_t A0[4], A1[4], Bf0[2], Bf1[2];
            A0[0] = *(const uint32_t*)&As[ra][k0];
            A0[1] = *(const uint32_t*)&As[ra + 8][k0];
            A0[2] = *(const uint32_t*)&As[ra][k0 + 8];
            A0[3] = *(const uint32_t*)&As[ra + 8][k0 + 8];
            A1[0] = *(const uint32_t*)&As[ra + 16][k0];
            A1[1] = *(const uint32_t*)&As[ra + 24][k0];
            A1[2] = *(const uint32_t*)&As[ra + 16][k0 + 8];
            A1[3] = *(const uint32_t*)&As[ra + 24][k0 + 8];
            int d0 = w * 16 + ra;
            Bf0[0] = *(const uint32_t*)&Bs[d0][k0];
            Bf0[1] = *(const uint32_t*)&Bs[d0][k0 + 8];
            Bf1[0] = *(const uint32_t*)&Bs[d0 + 8][k0];
            Bf1[1] = *(const uint32_t*)&Bs[d0 + 8][k0 + 8];
            mma16816(acc[0][0], A0, Bf0);
            mma16816(acc[0][1], A0, Bf1);
            mma16816(acc[1][0], A1, Bf0);
            mma16816(acc[1][1], A1, Bf1);
        }
        __syncthreads();
    }

    // ---- epilogue: merge partial V via red.global.add ----
    int orow = r0 + (lane >> 2);
    int ocol = w * 16 + 2 * (lane & 3);
    #pragma unroll
    for (int m = 0; m < 2; m++) {
        #pragma unroll
        for (int nt = 0; nt < 2; nt++) {
            float* a4 = acc[m][nt];
            int rr  = orow + m * 16;
            int ccg = ocol + nt * 8;
            atomicAdd(&out[rr * DOUT + ccg],           a4[0]);
            atomicAdd(&out[rr * DOUT + ccg + 1],       a4[1]);
            atomicAdd(&out[(rr + 8) * DOUT + ccg],     a4[2]);
            atomicAdd(&out[(rr + 8) * DOUT + ccg + 1], a4[3]);
        }
    }
}

// ---------------------------------------------------------------------------
extern "C" void kernel_launch(void* const* d_in, const int* in_sizes, int n_in,
                              void* d_out, int out_size) {
    const float* X0   = (const float*)d_in[0];
    const float* tvec = (const float*)d_in[1];
    const float* Wc_w = (const float*)d_in[2];
    const float* Wc_b = (const float*)d_in[3];
    const float* wvec = (const float*)d_in[4];
    const float* A    = (const float*)d_in[5];
    const float* Bp   = (const float*)d_in[6];
    float* out = (float*)d_out;

    angle_kernel<<<ROWS / 32, 128>>>(X0, Wc_w, Wc_b, wvec, tvec, A, Bp, out);
    fuse_kernel<<<(ROWS / 32) * 2, 128>>>(out);
}

// round 16
// speedup vs baseline: 1.1065x; 1.0144x over previous
#include <cuda_runtime.h>
#include <cuda_fp16.h>
#include <cstdint>

// Problem shape (fixed per metadata):
//   X0 [4,1024,256] f32, t [4,1] f32, Wc_w [128,256] f32, Wc_b [128] f32,
//   w [128] f32, A [64,128,6] f32, Bp [64,128,6] f32  ->  out [4,1024,64] f32
#define B_   4
#define S_   1024
#define ROWS 4096        // B_*S_
#define DIN  256
#define Q_   128
#define KF   6
#define DOUT 64
#define KSL  1536        // GEMM2: 1 fp16 slot per feature

// Scratch (no device allocs allowed)
__device__ float  g_angle[ROWS * Q_];          // 2 MB
__device__ __half g_bh[DOUT * KSL];            // 192 KB  [d][k] fp16 coeffs

// ---------------------------------------------------------------------------
// m16n8k16 fp16 MMA + ldmatrix helpers
// ---------------------------------------------------------------------------
__device__ __forceinline__ void mma16816(float* c, const uint32_t* a,
                                         const uint32_t* b) {
    asm volatile(
        "mma.sync.aligned.m16n8k16.row.col.f32.f16.f16.f32 "
        "{%0,%1,%2,%3}, {%4,%5,%6,%7}, {%8,%9}, {%0,%1,%2,%3};"
        : "+f"(c[0]), "+f"(c[1]), "+f"(c[2]), "+f"(c[3])
        : "r"(a[0]), "r"(a[1]), "r"(a[2]), "r"(a[3]), "r"(b[0]), "r"(b[1]));
}
__device__ __forceinline__ void ldsm_x4(uint32_t* r, uint32_t addr) {
    asm volatile("ldmatrix.sync.aligned.m8n8.x4.shared.b16 {%0,%1,%2,%3}, [%4];"
                 : "=r"(r[0]), "=r"(r[1]), "=r"(r[2]), "=r"(r[3]) : "r"(addr));
}
__device__ __forceinline__ uint32_t smem_u32(const void* p) {
    uint32_t a;
    asm("{ .reg .u64 t; cvta.to.shared.u64 t, %1; cvt.u32.u64 %0, t; }"
        : "=r"(a) : "l"(p));
    return a;
}

// ---------------------------------------------------------------------------
// Kernel 1: angle GEMM, q-SPLIT x2 (grid 256, 2 CTAs/SM co-resident).
// CTA (r,qh): rows r*32..+31, q-half qh*64..+63. Inline W split (each CTA
// stages only its own 64 W rows -> total W staging conserved). Double-
// buffered, 1 barrier/chunk, ldsm A frags.
// Tails: 192-elem g_bh fold slice + 1024-float out zero-init per CTA.
// ---------------------------------------------------------------------------
#define KP1 72

__global__ __launch_bounds__(128) void angle_kernel(
    const float* __restrict__ X0, const float* __restrict__ W,
    const float* __restrict__ bias, const float* __restrict__ wvec,
    const float* __restrict__ tvec,
    const float* __restrict__ A, const float* __restrict__ Bp,
    float* __restrict__ out)
{
    __shared__ __align__(16) __half Ws1[2][64][KP1];   // 18 KB
    __shared__ __align__(16) __half Ax1[2][32][KP1];   //  9.2 KB

    int tid  = threadIdx.x;
    int lane = tid & 31;
    int w    = tid >> 5;              // warp 0..3: q sub-range w*16 .. +15
    int r0   = (blockIdx.x >> 1) * 32;
    int qb   = (blockIdx.x & 1) * 64; // q-half base
    int ra   = lane >> 2;
    int cc   = 2 * (lane & 3);
    int lrow = (lane & 7) + ((lane >> 3) & 1) * 8;   // ldmatrix row-in-tile
    int lco  = (lane >> 4) * 8;                      // ldmatrix col offset

    float acc[2][2][4] = {};          // [mtile][ntile][frag]
    int xrow = tid >> 2;              // A staging row 0..31
    int kgrp = (tid & 3) * 8;         // f32 k offset (8 floats/thread)
    int wq   = tid >> 1;              // W staging local q 0..63
    int wjj  = (tid & 1) * 16;        // W staging k sub-offset (16 f32)

    auto stageA = [&](const float4& x0, const float4& x1, int buf) {
        float xf[8] = {x0.x, x0.y, x0.z, x0.w, x1.x, x1.y, x1.z, x1.w};
        uint32_t ph[4], pl[4];
        #pragma unroll
        for (int j = 0; j < 4; j++) {
            float a0 = xf[2 * j], a1 = xf[2 * j + 1];
            __half h0 = __float2half_rn(a0);
            __half l0 = __float2half_rn(a0 - __half2float(h0));
            __half h1 = __float2half_rn(a1);
            __half l1 = __float2half_rn(a1 - __half2float(h1));
            __half2 hh = __halves2half2(h0, h1);
            __half2 ll = __halves2half2(l0, l1);
            ph[j] = *(uint32_t*)&hh;
            pl[j] = *(uint32_t*)&ll;
        }
        *(uint4*)&Ax1[buf][xrow][kgrp]      = make_uint4(ph[0], ph[1], ph[2], ph[3]);
        *(uint4*)&Ax1[buf][xrow][32 + kgrp] = make_uint4(pl[0], pl[1], pl[2], pl[3]);
    };
    // split 16 f32 of W row wq -> wh cols wjj.., wl cols 32+wjj..
    auto stageW = [&](const float4* nwf, int buf) {
        const float* wf = (const float*)nwf;
        uint32_t whp[8], wlp[8];
        #pragma unroll
        for (int j = 0; j < 8; j++) {
            float a0 = wf[2 * j], a1 = wf[2 * j + 1];
            __half h0 = __float2half_rn(a0);
            __half l0 = __float2half_rn(a0 - __half2float(h0));
            __half h1 = __float2half_rn(a1);
            __half l1 = __float2half_rn(a1 - __half2float(h1));
            __half2 hh = __halves2half2(h0, h1);
            __half2 ll = __halves2half2(l0, l1);
            whp[j] = *(uint32_t*)&hh;
            wlp[j] = *(uint32_t*)&ll;
        }
        *(uint4*)&Ws1[buf][wq][wjj]          = make_uint4(whp[0], whp[1], whp[2], whp[3]);
        *(uint4*)&Ws1[buf][wq][wjj + 8]      = make_uint4(whp[4], whp[5], whp[6], whp[7]);
        *(uint4*)&Ws1[buf][wq][32 + wjj]     = make_uint4(wlp[0], wlp[1], wlp[2], wlp[3]);
        *(uint4*)&Ws1[buf][wq][32 + wjj + 8] = make_uint4(wlp[4], wlp[5], wlp[6], wlp[7]);
    };

    // ---- prologue: stage chunk 0, prefetch chunk 1 ----
    float4 nx0 = *(const float4*)&X0[(r0 + xrow) * DIN + kgrp];
    float4 nx1 = *(const float4*)&X0[(r0 + xrow) * DIN + kgrp + 4];
    float4 nwf[4];
    #pragma unroll
    for (int j = 0; j < 4; j++)
        nwf[j] = *(const float4*)&W[(qb + wq) * DIN + wjj + j * 4];
    stageA(nx0, nx1, 0);
    stageW(nwf, 0);
    nx0 = *(const float4*)&X0[(r0 + xrow) * DIN + 32 + kgrp];
    nx1 = *(const float4*)&X0[(r0 + xrow) * DIN + 32 + kgrp + 4];
    #pragma unroll
    for (int j = 0; j < 4; j++)
        nwf[j] = *(const float4*)&W[(qb + wq) * DIN + 32 + wjj + j * 4];
    __syncthreads();

    for (int c = 0; c < 8; c++) {
        if (c < 7) {
            stageA(nx0, nx1, (c + 1) & 1);
            stageW(nwf, (c + 1) & 1);
            if (c < 6) {
                nx0 = *(const float4*)&X0[(r0 + xrow) * DIN + (c + 2) * 32 + kgrp];
                nx1 = *(const float4*)&X0[(r0 + xrow) * DIN + (c + 2) * 32 + kgrp + 4];
                #pragma unroll
                for (int j = 0; j < 4; j++)
                    nwf[j] = *(const float4*)&W[(qb + wq) * DIN + (c + 2) * 32 + wjj + j * 4];
            }
        }

        // ---- MMA(c): 2 ktiles x {xh*wh, xh*wl, xl*wh} x 2m x 2n ----
        uint32_t axb = smem_u32(&Ax1[c & 1][0][0]);
        const __half (*Ws)[KP1] = Ws1[c & 1];
        #pragma unroll
        for (int kt = 0; kt < 2; kt++) {
            int khb = kt * 16;            // xh col base
            int klb = 32 + kt * 16;       // xl col base
            uint32_t A0h[4], A1h[4], A0l[4], A1l[4];
            ldsm_x4(A0h, axb + (uint32_t)((lrow * KP1 + khb + lco) * 2));
            ldsm_x4(A1h, axb + (uint32_t)(((16 + lrow) * KP1 + khb + lco) * 2));
            ldsm_x4(A0l, axb + (uint32_t)((lrow * KP1 + klb + lco) * 2));
            ldsm_x4(A1l, axb + (uint32_t)(((16 + lrow) * KP1 + klb + lco) * 2));
            int kh = khb + cc, kl = klb + cc;
            #pragma unroll
            for (int n = 0; n < 2; n++) {
                int q0 = w * 16 + n * 8 + ra;   // local q row in Ws
                uint32_t Bh[2], Bl[2];
                Bh[0] = *(const uint32_t*)&Ws[q0][kh];
                Bh[1] = *(const uint32_t*)&Ws[q0][kh + 8];
                Bl[0] = *(const uint32_t*)&Ws[q0][kl];
                Bl[1] = *(const uint32_t*)&Ws[q0][kl + 8];
                mma16816(acc[0][n], A0h, Bh);   // xh*wh
                mma16816(acc[1][n], A1h, Bh);
                mma16816(acc[0][n], A0h, Bl);   // xh*wl
                mma16816(acc[1][n], A1h, Bl);
                mma16816(acc[0][n], A0l, Bh);   // xl*wh
                mma16816(acc[1][n], A1l, Bh);
            }
        }
        __syncthreads();
    }

    // ---- epilogue: + bias + w*t -> g_angle ----
    float tb = tvec[r0 >> 10];
    #pragma unroll
    for (int n = 0; n < 2; n++) {
        int q = qb + w * 16 + n * 8 + cc;
        float b0 = __ldg(&bias[q])     + __ldg(&wvec[q]) * tb;
        float b1 = __ldg(&bias[q + 1]) + __ldg(&wvec[q + 1]) * tb;
        #pragma unroll
        for (int m = 0; m < 2; m++) {
            int rr = r0 + m * 16 + ra;
            float* a4 = acc[m][n];
            *(float2*)&g_angle[rr * Q_ + q]       = make_float2(a4[0] + b0, a4[1] + b1);
            *(float2*)&g_angle[(rr + 8) * Q_ + q] = make_float2(a4[2] + b0, a4[3] + b1);
        }
    }

    // ---- tail A: 192-element slice of the A,Bp fold (g_bh) ----
    #pragma unroll
    for (int j = 0; j < 2; j++) {
        int idx = j * 128 + tid;
        if (idx < 192) {
            int i = blockIdx.x * 192 + idx;           // 0 .. 49151
            int d   = i / (Q_ * KF);
            int rem = i - d * (Q_ * KF);              // q*6 + h
            float a = A[i], b = Bp[i];
            float sb, cb;
            __sincosf(b, &sb, &cb);
            __half2 hv = __floats2half2_rn(a * cb, a * sb);
            *(uint32_t*)&g_bh[d * KSL + rem * 2] = *(uint32_t*)&hv;
        }
    }

    // ---- tail B: zero this CTA's 1024-float slice of out (for atomics) ----
    {
        float4 z = make_float4(0.f, 0.f, 0.f, 0.f);
        float4* ob = (float4*)(out + blockIdx.x * 1024);
        ob[tid]       = z;
        ob[tid + 128] = z;
    }
}

// ---------------------------------------------------------------------------
// Kernel 2: fused feature-gen + HMMA GEMM2, K-SPLIT x4.
// 512 CTAs x 128 threads: CTA (r,kq) = rows (bid>>2)*32..+31, q-quarter
// kq*32..+31 (k-slots kq*384..+383), 2 chunks of 192 slots — per-chunk
// structure identical to the measured R10 loop. Partial V merged with
// red.global.add (out zeroed by angle tail). ~3.5 CTAs/SM.
// ---------------------------------------------------------------------------
#define KPAD   200
#define CHUNK_K 192
#define NCHUNK  2

__global__ __launch_bounds__(128) void fuse_kernel(float* __restrict__ out)
{
    __shared__ __half As[32][KPAD];   // 12.8 KB
    __shared__ __half Bs[64][KPAD];   // 25.6 KB

    int tid  = threadIdx.x;
    int lane = tid & 31;
    int w    = tid >> 5;
    int r0   = (blockIdx.x >> 2) * 32;
    int kq   = blockIdx.x & 3;        // K quarter
    int qb   = kq * 32;               // global q base of this quarter
    int kb   = kq * 384;              // global k-slot base
    int row  = lane;                  // featgen row
    int qlb  = w * 4;                 // featgen local-q base (4 q per thread)

    float acc[2][2][4] = {};

    // prologue prefetch: chunk 0
    uint4 nB[12];
    #pragma unroll
    for (int r = 0; r < 12; r++) {
        int idx = tid + 128 * r;
        int d   = idx / 24;
        int kc  = idx - d * 24;
        nB[r] = *(const uint4*)&g_bh[d * KSL + kb + kc * 8];
    }
    float4 nAng = *(const float4*)&g_angle[(r0 + row) * Q_ + qb + qlb];

    for (int c = 0; c < NCHUNK; c++) {
        // ---- features for 4 q's -> fp16, STS ----
        {
            float af[4] = {nAng.x, nAng.y, nAng.z, nAng.w};
            #pragma unroll
            for (int p = 0; p < 4; p++) {
                float a = af[p];
                // Cody-Waite reduction mod 2*pi (C1=6.28125: 9 mantissa bits)
                float n = rintf(a * 0.15915494309189535f);
                float rr = fmaf(n, -6.28125f, a);
                rr = fmaf(n, -1.9353071795864769e-3f, rr);
                float s1, c1;
                __sincosf(rr, &s1, &c1);
                float f[12];
                f[0] = s1; f[1] = c1;
                float sk = s1, ck = c1;
                #pragma unroll
                for (int h = 1; h < KF; h++) {
                    float sn = fmaf(sk, c1, ck * s1);
                    float cn = fmaf(ck, c1, -sk * s1);
                    f[2 * h] = sn; f[2 * h + 1] = cn;
                    sk = sn; ck = cn;
                }
                uint32_t hv[6];
                #pragma unroll
                for (int g = 0; g < 6; g++) {
                    __half2 h2 = __floats2half2_rn(f[2 * g], f[2 * g + 1]);
                    hv[g] = *(uint32_t*)&h2;
                }
                int kl = (qlb + p) * 12;
                uint64_t* dst = (uint64_t*)&As[row][kl];
                dst[0] = (uint64_t)hv[0] | ((uint64_t)hv[1] << 32);
                dst[1] = (uint64_t)hv[2] | ((uint64_t)hv[3] << 32);
                dst[2] = (uint64_t)hv[4] | ((uint64_t)hv[5] << 32);
            }
        }
        // ---- stage B chunk ----
        #pragma unroll
        for (int r = 0; r < 12; r++) {
            int idx = tid + 128 * r;
            int d   = idx / 24;
            int kc  = idx - d * 24;
            *(uint4*)&Bs[d][kc * 8] = nB[r];
        }
        __syncthreads();

        // ---- prefetch next chunk ----
        if (c < NCHUNK - 1) {
            #pragma unroll
            for (int r = 0; r < 12; r++) {
                int idx = tid + 128 * r;
                int d   = idx / 24;
                int kc  = idx - d * 24;
                nB[r] = *(const uint4*)&g_bh[d * KSL + kb + (c + 1) * CHUNK_K + kc * 8];
            }
            nAng = *(const float4*)&g_angle[(r0 + row) * Q_ + qb + (c + 1) * 16 + qlb];
        }

        // ---- MMA: 12 ktiles x (2m x 2n) ----
        int ra = lane >> 2;
        int cc = 2 * (lane & 3);
        #pragma unroll
        for (int kt = 0; kt < 12; kt++) {
            int k0 = kt * 16 + cc;
            uint32_t A0[4], A1[4], Bf0[2], Bf1[2];
            A0[0] = *(const uint32_t*)&As[ra][k0];
            A0[1] = *(const uint32_t*)&As[ra + 8][k0];
            A0[2] = *(const uint32_t*)&As[ra][k0 + 8];
            A0[3] = *(const uint32_t*)&As[ra + 8][k0 + 8];
            A1[0] = *(const uint32_t*)&As[ra + 16][k0];
            A1[1] = *(const uint32_t*)&As[ra + 24][k0];
            A1[2] = *(const uint32_t*)&As[ra + 16][k0 + 8];
            A1[3] = *(const uint32_t*)&As[ra + 24][k0 + 8];
            int d0 = w * 16 + ra;
            Bf0[0] = *(const uint32_t*)&Bs[d0][k0];
            Bf0[1] = *(const uint32_t*)&Bs[d0][k0 + 8];
            Bf1[0] = *(const uint32_t*)&Bs[d0 + 8][k0];
            Bf1[1] = *(const uint32_t*)&Bs[d0 + 8][k0 + 8];
            mma16816(acc[0][0], A0, Bf0);
            mma16816(acc[0][1], A0, Bf1);
            mma16816(acc[1][0], A1, Bf0);
            mma16816(acc[1][1], A1, Bf1);
        }
        __syncthreads();
    }

    // ---- epilogue: merge partial V via red.global.add ----
    int orow = r0 + (lane >> 2);
    int ocol = w * 16 + 2 * (lane & 3);
    #pragma unroll
    for (int m = 0; m < 2; m++) {
        #pragma unroll
        for (int nt = 0; nt < 2; nt++) {
            float* a4 = acc[m][nt];
            int rr  = orow + m * 16;
            int ccg = ocol + nt * 8;
            atomicAdd(&out[rr * DOUT + ccg],           a4[0]);
            atomicAdd(&out[rr * DOUT + ccg + 1],       a4[1]);
            atomicAdd(&out[(rr + 8) * DOUT + ccg],     a4[2]);
            atomicAdd(&out[(rr + 8) * DOUT + ccg + 1], a4[3]);
        }
    }
}

// ---------------------------------------------------------------------------
extern "C" void kernel_launch(void* const* d_in, const int* in_sizes, int n_in,
                              void* d_out, int out_size) {
    const float* X0   = (const float*)d_in[0];
    const float* tvec = (const float*)d_in[1];
    const float* Wc_w = (const float*)d_in[2];
    const float* Wc_b = (const float*)d_in[3];
    const float* wvec = (const float*)d_in[4];
    const float* A    = (const float*)d_in[5];
    const float* Bp   = (const float*)d_in[6];
    float* out = (float*)d_out;

    angle_kernel<<<(ROWS / 32) * 2, 128>>>(X0, Wc_w, Wc_b, wvec, tvec, A, Bp, out);
    fuse_kernel<<<(ROWS / 32) * 4, 128>>>(out);
}

// round 17
// speedup vs baseline: 1.1652x; 1.0530x over previous
#include <cuda_runtime.h>
#include <cuda_fp16.h>
#include <cstdint>

// Problem shape (fixed per metadata):
//   X0 [4,1024,256] f32, t [4,1] f32, Wc_w [128,256] f32, Wc_b [128] f32,
//   w [128] f32, A [64,128,6] f32, Bp [64,128,6] f32  ->  out [4,1024,64] f32
#define B_   4
#define S_   1024
#define ROWS 4096        // B_*S_
#define DIN  256
#define Q_   128
#define KF   6
#define DOUT 64
#define KSL  1536        // GEMM2: 1 fp16 slot per feature

// Scratch (no device allocs allowed)
__device__ float  g_angle[ROWS * Q_];          // 2 MB
__device__ __half g_bh[DOUT * KSL];            // 192 KB  [d][k] fp16 coeffs

// ---------------------------------------------------------------------------
// m16n8k16 fp16 MMA + ldmatrix helpers
// ---------------------------------------------------------------------------
__device__ __forceinline__ void mma16816(float* c, const uint32_t* a,
                                         const uint32_t* b) {
    asm volatile(
        "mma.sync.aligned.m16n8k16.row.col.f32.f16.f16.f32 "
        "{%0,%1,%2,%3}, {%4,%5,%6,%7}, {%8,%9}, {%0,%1,%2,%3};"
        : "+f"(c[0]), "+f"(c[1]), "+f"(c[2]), "+f"(c[3])
        : "r"(a[0]), "r"(a[1]), "r"(a[2]), "r"(a[3]), "r"(b[0]), "r"(b[1]));
}
__device__ __forceinline__ void ldsm_x4(uint32_t* r, uint32_t addr) {
    asm volatile("ldmatrix.sync.aligned.m8n8.x4.shared.b16 {%0,%1,%2,%3}, [%4];"
                 : "=r"(r[0]), "=r"(r[1]), "=r"(r[2]), "=r"(r[3]) : "r"(addr));
}
__device__ __forceinline__ uint32_t smem_u32(const void* p) {
    uint32_t a;
    asm("{ .reg .u64 t; cvta.to.shared.u64 t, %1; cvt.u32.u64 %0, t; }"
        : "=r"(a) : "l"(p));
    return a;
}

// ---------------------------------------------------------------------------
// Kernel 1: angle GEMM, q-SPLIT x2 (R16 variant — measured best).
// CTA (r,qh): rows r*32..+31, q-half qh*64..+63. Inline W split. Double-
// buffered, 1 barrier/chunk, ldsm A frags.
// Tails: 192-elem g_bh fold slice + 1024-float out zero-init per CTA.
// ---------------------------------------------------------------------------
#define KP1 72

__global__ __launch_bounds__(128) void angle_kernel(
    const float* __restrict__ X0, const float* __restrict__ W,
    const float* __restrict__ bias, const float* __restrict__ wvec,
    const float* __restrict__ tvec,
    const float* __restrict__ A, const float* __restrict__ Bp,
    float* __restrict__ out)
{
    __shared__ __align__(16) __half Ws1[2][64][KP1];   // 18 KB
    __shared__ __align__(16) __half Ax1[2][32][KP1];   //  9.2 KB

    int tid  = threadIdx.x;
    int lane = tid & 31;
    int w    = tid >> 5;              // warp 0..3: q sub-range w*16 .. +15
    int r0   = (blockIdx.x >> 1) * 32;
    int qb   = (blockIdx.x & 1) * 64; // q-half base
    int ra   = lane >> 2;
    int cc   = 2 * (lane & 3);
    int lrow = (lane & 7) + ((lane >> 3) & 1) * 8;   // ldmatrix row-in-tile
    int lco  = (lane >> 4) * 8;                      // ldmatrix col offset

    float acc[2][2][4] = {};          // [mtile][ntile][frag]
    int xrow = tid >> 2;              // A staging row 0..31
    int kgrp = (tid & 3) * 8;         // f32 k offset (8 floats/thread)
    int wq   = tid >> 1;              // W staging local q 0..63
    int wjj  = (tid & 1) * 16;        // W staging k sub-offset (16 f32)

    auto stageA = [&](const float4& x0, const float4& x1, int buf) {
        float xf[8] = {x0.x, x0.y, x0.z, x0.w, x1.x, x1.y, x1.z, x1.w};
        uint32_t ph[4], pl[4];
        #pragma unroll
        for (int j = 0; j < 4; j++) {
            float a0 = xf[2 * j], a1 = xf[2 * j + 1];
            __half h0 = __float2half_rn(a0);
            __half l0 = __float2half_rn(a0 - __half2float(h0));
            __half h1 = __float2half_rn(a1);
            __half l1 = __float2half_rn(a1 - __half2float(h1));
            __half2 hh = __halves2half2(h0, h1);
            __half2 ll = __halves2half2(l0, l1);
            ph[j] = *(uint32_t*)&hh;
            pl[j] = *(uint32_t*)&ll;
        }
        *(uint4*)&Ax1[buf][xrow][kgrp]      = make_uint4(ph[0], ph[1], ph[2], ph[3]);
        *(uint4*)&Ax1[buf][xrow][32 + kgrp] = make_uint4(pl[0], pl[1], pl[2], pl[3]);
    };
    auto stageW = [&](const float4* nwf, int buf) {
        const float* wf = (const float*)nwf;
        uint32_t whp[8], wlp[8];
        #pragma unroll
        for (int j = 0; j < 8; j++) {
            float a0 = wf[2 * j], a1 = wf[2 * j + 1];
            __half h0 = __float2half_rn(a0);
            __half l0 = __float2half_rn(a0 - __half2float(h0));
            __half h1 = __float2half_rn(a1);
            __half l1 = __float2half_rn(a1 - __half2float(h1));
            __half2 hh = __halves2half2(h0, h1);
            __half2 ll = __halves2half2(l0, l1);
            whp[j] = *(uint32_t*)&hh;
            wlp[j] = *(uint32_t*)&ll;
        }
        *(uint4*)&Ws1[buf][wq][wjj]          = make_uint4(whp[0], whp[1], whp[2], whp[3]);
        *(uint4*)&Ws1[buf][wq][wjj + 8]      = make_uint4(whp[4], whp[5], whp[6], whp[7]);
        *(uint4*)&Ws1[buf][wq][32 + wjj]     = make_uint4(wlp[0], wlp[1], wlp[2], wlp[3]);
        *(uint4*)&Ws1[buf][wq][32 + wjj + 8] = make_uint4(wlp[4], wlp[5], wlp[6], wlp[7]);
    };

    // ---- prologue: stage chunk 0, prefetch chunk 1 ----
    float4 nx0 = *(const float4*)&X0[(r0 + xrow) * DIN + kgrp];
    float4 nx1 = *(const float4*)&X0[(r0 + xrow) * DIN + kgrp + 4];
    float4 nwf[4];
    #pragma unroll
    for (int j = 0; j < 4; j++)
        nwf[j] = *(const float4*)&W[(qb + wq) * DIN + wjj + j * 4];
    stageA(nx0, nx1, 0);
    stageW(nwf, 0);
    nx0 = *(const float4*)&X0[(r0 + xrow) * DIN + 32 + kgrp];
    nx1 = *(const float4*)&X0[(r0 + xrow) * DIN + 32 + kgrp + 4];
    #pragma unroll
    for (int j = 0; j < 4; j++)
        nwf[j] = *(const float4*)&W[(qb + wq) * DIN + 32 + wjj + j * 4];
    __syncthreads();

    for (int c = 0; c < 8; c++) {
        if (c < 7) {
            stageA(nx0, nx1, (c + 1) & 1);
            stageW(nwf, (c + 1) & 1);
            if (c < 6) {
                nx0 = *(const float4*)&X0[(r0 + xrow) * DIN + (c + 2) * 32 + kgrp];
                nx1 = *(const float4*)&X0[(r0 + xrow) * DIN + (c + 2) * 32 + kgrp + 4];
                #pragma unroll
                for (int j = 0; j < 4; j++)
                    nwf[j] = *(const float4*)&W[(qb + wq) * DIN + (c + 2) * 32 + wjj + j * 4];
            }
        }

        // ---- MMA(c): 2 ktiles x {xh*wh, xh*wl, xl*wh} x 2m x 2n ----
        uint32_t axb = smem_u32(&Ax1[c & 1][0][0]);
        const __half (*Ws)[KP1] = Ws1[c & 1];
        #pragma unroll
        for (int kt = 0; kt < 2; kt++) {
            int khb = kt * 16;            // xh col base
            int klb = 32 + kt * 16;       // xl col base
            uint32_t A0h[4], A1h[4], A0l[4], A1l[4];
            ldsm_x4(A0h, axb + (uint32_t)((lrow * KP1 + khb + lco) * 2));
            ldsm_x4(A1h, axb + (uint32_t)(((16 + lrow) * KP1 + khb + lco) * 2));
            ldsm_x4(A0l, axb + (uint32_t)((lrow * KP1 + klb + lco) * 2));
            ldsm_x4(A1l, axb + (uint32_t)(((16 + lrow) * KP1 + klb + lco) * 2));
            int kh = khb + cc, kl = klb + cc;
            #pragma unroll
            for (int n = 0; n < 2; n++) {
                int q0 = w * 16 + n * 8 + ra;   // local q row in Ws
                uint32_t Bh[2], Bl[2];
                Bh[0] = *(const uint32_t*)&Ws[q0][kh];
                Bh[1] = *(const uint32_t*)&Ws[q0][kh + 8];
                Bl[0] = *(const uint32_t*)&Ws[q0][kl];
                Bl[1] = *(const uint32_t*)&Ws[q0][kl + 8];
                mma16816(acc[0][n], A0h, Bh);   // xh*wh
                mma16816(acc[1][n], A1h, Bh);
                mma16816(acc[0][n], A0h, Bl);   // xh*wl
                mma16816(acc[1][n], A1h, Bl);
                mma16816(acc[0][n], A0l, Bh);   // xl*wh
                mma16816(acc[1][n], A1l, Bh);
            }
        }
        __syncthreads();
    }

    // ---- epilogue: + bias + w*t -> g_angle ----
    float tb = tvec[r0 >> 10];
    #pragma unroll
    for (int n = 0; n < 2; n++) {
        int q = qb + w * 16 + n * 8 + cc;
        float b0 = __ldg(&bias[q])     + __ldg(&wvec[q]) * tb;
        float b1 = __ldg(&bias[q + 1]) + __ldg(&wvec[q + 1]) * tb;
        #pragma unroll
        for (int m = 0; m < 2; m++) {
            int rr = r0 + m * 16 + ra;
            float* a4 = acc[m][n];
            *(float2*)&g_angle[rr * Q_ + q]       = make_float2(a4[0] + b0, a4[1] + b1);
            *(float2*)&g_angle[(rr + 8) * Q_ + q] = make_float2(a4[2] + b0, a4[3] + b1);
        }
    }

    // ---- tail A: 192-element slice of the A,Bp fold (g_bh) ----
    #pragma unroll
    for (int j = 0; j < 2; j++) {
        int idx = j * 128 + tid;
        if (idx < 192) {
            int i = blockIdx.x * 192 + idx;           // 0 .. 49151
            int d   = i / (Q_ * KF);
            int rem = i - d * (Q_ * KF);              // q*6 + h
            float a = A[i], b = Bp[i];
            float sb, cb;
            __sincosf(b, &sb, &cb);
            __half2 hv = __floats2half2_rn(a * cb, a * sb);
            *(uint32_t*)&g_bh[d * KSL + rem * 2] = *(uint32_t*)&hv;
        }
    }

    // ---- tail B: zero this CTA's 1024-float slice of out (for atomics) ----
    {
        float4 z = make_float4(0.f, 0.f, 0.f, 0.f);
        float4* ob = (float4*)(out + blockIdx.x * 1024);
        ob[tid]       = z;
        ob[tid + 128] = z;
    }
}

// ---------------------------------------------------------------------------
// Kernel 2: fused feature-gen + HMMA GEMM2, K-SPLIT x2 (R15 variant —
// measured 11.4us, the best fuse). 256 CTAs x 128 threads: CTA (r,h) =
// rows (bid>>1)*32..+31, q-half h=bid&1, 4 chunks of 192 slots. Partial V
// merged with red.global.add (out zeroed by angle tail).
// ---------------------------------------------------------------------------
#define KPAD   200
#define CHUNK_K 192
#define NCHUNK  4

__global__ __launch_bounds__(128) void fuse_kernel(float* __restrict__ out)
{
    __shared__ __half As[32][KPAD];   // 12.8 KB
    __shared__ __half Bs[64][KPAD];   // 25.6 KB

    int tid  = threadIdx.x;
    int lane = tid & 31;
    int w    = tid >> 5;
    int r0   = (blockIdx.x >> 1) * 32;
    int kh   = blockIdx.x & 1;        // K half
    int qb   = kh * 64;               // global q base of this half
    int kb   = kh * 768;              // global k-slot base
    int row  = lane;                  // featgen row
    int qlb  = w * 4;                 // featgen local-q base (4 q per thread)

    float acc[2][2][4] = {};

    // prologue prefetch: chunk 0
    uint4 nB[12];
    #pragma unroll
    for (int r = 0; r < 12; r++) {
        int idx = tid + 128 * r;
        int d   = idx / 24;
        int kc  = idx - d * 24;
        nB[r] = *(const uint4*)&g_bh[d * KSL + kb + kc * 8];
    }
    float4 nAng = *(const float4*)&g_angle[(r0 + row) * Q_ + qb + qlb];

    for (int c = 0; c < NCHUNK; c++) {
        // ---- features for 4 q's -> fp16, STS ----
        {
            float af[4] = {nAng.x, nAng.y, nAng.z, nAng.w};
            #pragma unroll
            for (int p = 0; p < 4; p++) {
                float a = af[p];
                // Cody-Waite reduction mod 2*pi (C1=6.28125: 9 mantissa bits)
                float n = rintf(a * 0.15915494309189535f);
                float rr = fmaf(n, -6.28125f, a);
                rr = fmaf(n, -1.9353071795864769e-3f, rr);
                float s1, c1;
                __sincosf(rr, &s1, &c1);
                float f[12];
                f[0] = s1; f[1] = c1;
                float sk = s1, ck = c1;
                #pragma unroll
                for (int h = 1; h < KF; h++) {
                    float sn = fmaf(sk, c1, ck * s1);
                    float cn = fmaf(ck, c1, -sk * s1);
                    f[2 * h] = sn; f[2 * h + 1] = cn;
                    sk = sn; ck = cn;
                }
                uint32_t hv[6];
                #pragma unroll
                for (int g = 0; g < 6; g++) {
                    __half2 h2 = __floats2half2_rn(f[2 * g], f[2 * g + 1]);
                    hv[g] = *(uint32_t*)&h2;
                }
                int kl = (qlb + p) * 12;
                uint64_t* dst = (uint64_t*)&As[row][kl];
                dst[0] = (uint64_t)hv[0] | ((uint64_t)hv[1] << 32);
                dst[1] = (uint64_t)hv[2] | ((uint64_t)hv[3] << 32);
                dst[2] = (uint64_t)hv[4] | ((uint64_t)hv[5] << 32);
            }
        }
        // ---- stage B chunk ----
        #pragma unroll
        for (int r = 0; r < 12; r++) {
            int idx = tid + 128 * r;
            int d   = idx / 24;
            int kc  = idx - d * 24;
            *(uint4*)&Bs[d][kc * 8] = nB[r];
        }
        __syncthreads();

        // ---- prefetch next chunk ----
        if (c < NCHUNK - 1) {
            #pragma unroll
            for (int r = 0; r < 12; r++) {
                int idx = tid + 128 * r;
                int d   = idx / 24;
                int kc  = idx - d * 24;
                nB[r] = *(const uint4*)&g_bh[d * KSL + kb + (c + 1) * CHUNK_K + kc * 8];
            }
            nAng = *(const float4*)&g_angle[(r0 + row) * Q_ + qb + (c + 1) * 16 + qlb];
        }

        // ---- MMA: 12 ktiles x (2m x 2n) ----
        int ra = lane >> 2;
        int cc = 2 * (lane & 3);
        #pragma unroll
        for (int kt = 0; kt < 12; kt++) {
            int k0 = kt * 16 + cc;
            uint32_t A0[4], A1[4], Bf0[2], Bf1[2];
            A0[0] = *(const uint32_t*)&As[ra][k0];
            A0[1] = *(const uint32_t*)&As[ra + 8][k0];
            A0[2] = *(const uint32_t*)&As[ra][k0 + 8];
            A0[3] = *(const uint32_t*)&As[ra + 8][k0 + 8];
            A1[0] = *(const uint32_t*)&As[ra + 16][k0];
            A1[1] = *(const uint32_t*)&As[ra + 24][k0];
            A1[2] = *(const uint32_t*)&As[ra + 16][k0 + 8];
            A1[3] = *(const uint32_t*)&As[ra + 24][k0 + 8];
            int d0 = w * 16 + ra;
            Bf0[0] = *(const uint32_t*)&Bs[d0][k0];
            Bf0[1] = *(const uint32_t*)&Bs[d0][k0 + 8];
            Bf1[0] = *(const uint32_t*)&Bs[d0 + 8][k0];
            Bf1[1] = *(const uint32_t*)&Bs[d0 + 8][k0 + 8];
            mma16816(acc[0][0], A0, Bf0);
            mma16816(acc[0][1], A0, Bf1);
            mma16816(acc[1][0], A1, Bf0);
            mma16816(acc[1][1], A1, Bf1);
        }
        __syncthreads();
    }

    // ---- epilogue: merge partial V via red.global.add ----
    int orow = r0 + (lane >> 2);
    int ocol = w * 16 + 2 * (lane & 3);
    #pragma unroll
    for (int m = 0; m < 2; m++) {
        #pragma unroll
        for (int nt = 0; nt < 2; nt++) {
            float* a4 = acc[m][nt];
            int rr  = orow + m * 16;
            int ccg = ocol + nt * 8;
            atomicAdd(&out[rr * DOUT + ccg],           a4[0]);
            atomicAdd(&out[rr * DOUT + ccg + 1],       a4[1]);
            atomicAdd(&out[(rr + 8) * DOUT + ccg],     a4[2]);
            atomicAdd(&out[(rr + 8) * DOUT + ccg + 1], a4[3]);
        }
    }
}

// ---------------------------------------------------------------------------
extern "C" void kernel_launch(void* const* d_in, const int* in_sizes, int n_in,
                              void* d_out, int out_size) {
    const float* X0   = (const float*)d_in[0];
    const float* tvec = (const float*)d_in[1];
    const float* Wc_w = (const float*)d_in[2];
    const float* Wc_b = (const float*)d_in[3];
    const float* wvec = (const float*)d_in[4];
    const float* A    = (const float*)d_in[5];
    const float* Bp   = (const float*)d_in[6];
    float* out = (float*)d_out;

    angle_kernel<<<(ROWS / 32) * 2, 128>>>(X0, Wc_w, Wc_b, wvec, tvec, A, Bp, out);
    fuse_kernel<<<(ROWS / 32) * 2, 128>>>(out);
}